// round 12
// baseline (speedup 1.0000x reference)
#include <cuda_runtime.h>

#define NV 16384
#define CC 512
#define KK 64
#define BB 64
#define SMS 68                  // smem row stride in floats (bank-conflict pad)
#define BUDGETF 8.0f

// Double-buffered global state: blocks read parity p, write p^1, so halo
// reads never race with neighbor-block writes within a launch.
__device__ float g_msg[2][BB * CC * KK];
__device__ float g_lam[2][BB * CC * KK];

__device__ __forceinline__ float qsum(float v) {
    v += __shfl_xor_sync(0xffffffffu, v, 1);
    v += __shfl_xor_sync(0xffffffffu, v, 2);
    return v;
}
__device__ __forceinline__ float qmax(float v) {
    v = fmaxf(v, __shfl_xor_sync(0xffffffffu, v, 1));
    v = fmaxf(v, __shfl_xor_sync(0xffffffffu, v, 2));
    return v;
}

// One block: batch b, constraints [c0, c0+64) valid, rows [c0-H, c0+64+H) held.
// Runs T fused ADMM iterations; msg ping-pongs in smem, lam/scores in regs.
// LAST: after the iterations, emit u directly from smem (no state writeback).
template <int H, bool FIRST, bool LAST>
__global__ void __launch_bounds__(4 * (64 + 2 * H), 3)
fused_admm(const float* __restrict__ scores, float* __restrict__ out,
           int p, int T, int nbis)
{
    constexpr int NR = 64 + 2 * H;
    __shared__ float s_msg[2][NR][SMS];

    const int t = threadIdx.x;
    const int r = t >> 2;                 // local row 0..NR-1
    const int g = t & 3;                  // quarter-row, k in [16g,16g+16)
    const int b = blockIdx.x >> 3;
    const int c0 = (blockIdx.x & 7) << 6;
    const int c = (c0 - H + r) & (CC - 1);
    const int grow = ((b << 9) + c) * KK + (g << 4);   // global row-slice offset

    // ---- scores into registers (window is 16-aligned, never straddles NV) ----
    float sc[16];
    {
        const int nb = ((c << 5) + (g << 4)) & (NV - 1);
        const float4* sp = (const float4*)(scores + b * NV + nb);
#pragma unroll
        for (int q = 0; q < 4; q++) {
            float4 v = sp[q];
            sc[4 * q] = v.x; sc[4 * q + 1] = v.y; sc[4 * q + 2] = v.z; sc[4 * q + 3] = v.w;
        }
    }

    // ---- lam into registers, msg into smem buffer 0 ----
    float lam[16];
    if (FIRST) {
#pragma unroll
        for (int k = 0; k < 16; k++) lam[k] = 0.f;
        float4* d = (float4*)&s_msg[0][r][g << 4];
#pragma unroll
        for (int q = 0; q < 4; q++) d[q] = make_float4(0.f, 0.f, 0.f, 0.f);
    } else {
        const float4* lp = (const float4*)(g_lam[p] + grow);
        const float4* mp = (const float4*)(g_msg[p] + grow);
        float4* d = (float4*)&s_msg[0][r][g << 4];
#pragma unroll
        for (int q = 0; q < 4; q++) {
            float4 lv = lp[q];
            lam[4 * q] = lv.x; lam[4 * q + 1] = lv.y; lam[4 * q + 2] = lv.z; lam[4 * q + 3] = lv.w;
            d[q] = mp[q];
        }
    }
    __syncthreads();

    // neighbor row (clamped; clamped rows are halo-garbage and never written back)
    const int rn = (g < 2) ? ((r > 0) ? r - 1 : 0) : ((r < NR - 1) ? r + 1 : NR - 1);
    const int kn = (g < 2) ? ((g << 4) + 32) : ((g - 2) << 4);

    for (int it = 0; it < T; ++it) {
        const int sb = it & 1;
        const float4* mo = (const float4*)&s_msg[sb][r][g << 4];
        const float4* mn = (const float4*)&s_msg[sb][rn][kn];

        float a[16];
#pragma unroll
        for (int q = 0; q < 4; q++) {
            float4 o = mo[q];
            float4 n = mn[q];
            a[4 * q + 0] = __saturatef((sc[4 * q + 0] + o.x + n.x) * 0.5f) + lam[4 * q + 0];
            a[4 * q + 1] = __saturatef((sc[4 * q + 1] + o.y + n.y) * 0.5f) + lam[4 * q + 1];
            a[4 * q + 2] = __saturatef((sc[4 * q + 2] + o.z + n.z) * 0.5f) + lam[4 * q + 2];
            a[4 * q + 3] = __saturatef((sc[4 * q + 3] + o.w + n.w) * 0.5f) + lam[4 * q + 3];
        }

        // feasibility
        float f0 = 0.f, f1 = 0.f, f2 = 0.f, f3 = 0.f;
#pragma unroll
        for (int k = 0; k < 16; k += 4) {
            f0 += __saturatef(a[k]);     f1 += __saturatef(a[k + 1]);
            f2 += __saturatef(a[k + 2]); f3 += __saturatef(a[k + 3]);
        }
        const bool feas = qsum((f0 + f1) + (f2 + f3)) <= BUDGETF;

        float tau = 0.f;
        if (!__all_sync(0xffffffffu, feas)) {
            // Infeasible row => s(0) > budget, so lo = 0 is a valid lower
            // bracket; s(max(a)) = 0 < budget for the upper.
            float mx1 = fmaxf(fmaxf(a[0], a[1]), fmaxf(a[2], a[3]));
#pragma unroll
            for (int k = 4; k < 16; k += 4)
                mx1 = fmaxf(mx1, fmaxf(fmaxf(a[k], a[k + 1]), fmaxf(a[k + 2], a[k + 3])));
            float lo = 0.0f;
            float hi = qmax(mx1);

#pragma unroll 1
            for (int qq = 0; qq < nbis; ++qq) {
                const float mid = 0.5f * (lo + hi);
                float t0 = 0.f, t1 = 0.f, t2 = 0.f, t3 = 0.f;
#pragma unroll
                for (int k = 0; k < 16; k += 4) {
                    t0 += __saturatef(a[k] - mid);
                    t1 += __saturatef(a[k + 1] - mid);
                    t2 += __saturatef(a[k + 2] - mid);
                    t3 += __saturatef(a[k + 3] - mid);
                }
                const float s = qsum((t0 + t1) + (t2 + t3));   // group-uniform
                if (s > BUDGETF) lo = mid; else hi = mid;
            }
            const float tau0 = 0.5f * (lo + hi);

            // Newton polish on the active set (matches reference)
            float na = 0.f, gs = 0.f;
#pragma unroll
            for (int k = 0; k < 16; k++) {
                const float d = a[k] - tau0;
                na += (d > 0.f && d < 1.f) ? 1.f : 0.f;
                gs += __saturatef(d);
            }
            const float nact = fmaxf(qsum(na), 1.0f);
            tau = tau0 + (qsum(gs) - BUDGETF) / nact;
        }

        // z, lam' = a - z, msg' = 2z - a
        float4* dst = (float4*)&s_msg[sb ^ 1][r][g << 4];
#pragma unroll
        for (int q = 0; q < 4; q++) {
            float mg[4];
#pragma unroll
            for (int j = 0; j < 4; j++) {
                const float ak = a[4 * q + j];
                const float zz = feas ? __saturatef(ak) : __saturatef(ak - tau);
                lam[4 * q + j] = ak - zz;
                mg[j] = zz - (ak - zz);
            }
            dst[q] = make_float4(mg[0], mg[1], mg[2], mg[3]);
        }
        __syncthreads();
    }

    if (!LAST) {
        // ---- write back valid rows only (valid after T <= H iterations) ----
        if (r >= H && r < H + 64) {
            const int fb = T & 1;
            float4* gm = (float4*)(g_msg[p ^ 1] + grow);
            float4* gl = (float4*)(g_lam[p ^ 1] + grow);
            const float4* sm = (const float4*)&s_msg[fb][r][g << 4];
#pragma unroll
            for (int q = 0; q < 4; q++) {
                gm[q] = sm[q];
                gl[q] = make_float4(lam[4 * q], lam[4 * q + 1], lam[4 * q + 2], lam[4 * q + 3]);
            }
        }
    } else {
        // ---- emit u directly: u[b, 32c + j] = sat((scores + msg[c][j] + msg[c-1][j+32])/2)
        // thread (r, g), r in [H, H+64): 8 outputs j = 8g .. 8g+7.
        // Rows c and c-1 valid: need rows [H-1, H+64) valid, i.e. T <= H-1.
        if (r >= H && r < H + 64) {
            const int fb = T & 1;
            const float* m_c  = &s_msg[fb][r][g << 3];          // msg[c][8g + jj], 8g<32
            const float* m_cm = &s_msg[fb][r - 1][(g << 3) + 32];
            const int n0 = (c << 5) + (g << 3);                  // c < 512 so n0 < NV
            const float4* sp = (const float4*)(scores + b * NV + n0);
            float4* op = (float4*)(out + b * NV + n0);
#pragma unroll
            for (int q = 0; q < 2; q++) {
                float4 sv = sp[q];
                float4 u;
                u.x = __saturatef((sv.x + m_c[4 * q + 0] + m_cm[4 * q + 0]) * 0.5f);
                u.y = __saturatef((sv.y + m_c[4 * q + 1] + m_cm[4 * q + 1]) * 0.5f);
                u.z = __saturatef((sv.z + m_c[4 * q + 2] + m_cm[4 * q + 2]) * 0.5f);
                u.w = __saturatef((sv.w + m_c[4 * q + 3] + m_cm[4 * q + 3]) * 0.5f);
                op[q] = u;
            }
        }
    }
}

extern "C" void kernel_launch(void* const* d_in, const int* in_sizes, int n_in,
                              void* d_out, int out_size)
{
    const float* scores = (const float*)d_in[0];
    if (n_in > 1 && in_sizes[0] == CC * KK) scores = (const float*)d_in[1];
    float* out = (float*)d_out;

    // 25 iterations = 8 + 8 + 9.
    // L1/L2: halo 8, 15 bisections (mid-trajectory; noise damped by ADMM).
    // L3:   halo 12, T=9 (needs T <= H-1 = 11 for u-emission), 18 bisections
    //       (validated exact class for the output-determining iterations).
    fused_admm< 8, true , false><<<512, 320>>>(scores, out, 0, 8, 15);  // writes parity 1
    fused_admm< 8, false, false><<<512, 320>>>(scores, out, 1, 8, 15);  // writes parity 0
    fused_admm<12, false, true ><<<512, 352>>>(scores, out, 0, 9, 18);  // emits u
}

// round 13
// speedup vs baseline: 1.6936x; 1.6936x over previous
#include <cuda_runtime.h>

#define NV 16384
#define CC 512
#define KK 64
#define BB 64
#define N_ROWS 80               // 8 halo + 64 valid + 8 halo
#define HALO 8
#define SMS 68                  // smem row stride in floats (bank-conflict pad)
#define BUDGETF 8.0f

// Double-buffered global state: blocks read parity p, write p^1, so halo
// reads never race with neighbor-block writes within a launch.
__device__ float g_msg[2][BB * CC * KK];
__device__ float g_lam[2][BB * CC * KK];

__device__ __forceinline__ float qsum(float v) {
    v += __shfl_xor_sync(0xffffffffu, v, 1);
    v += __shfl_xor_sync(0xffffffffu, v, 2);
    return v;
}
__device__ __forceinline__ float qmax(float v) {
    v = fmaxf(v, __shfl_xor_sync(0xffffffffu, v, 1));
    v = fmaxf(v, __shfl_xor_sync(0xffffffffu, v, 2));
    return v;
}

// One block: batch b, constraints [c0, c0+64) valid, rows [c0-8, c0+72) held.
// Runs T fused ADMM iterations; msg ping-pongs in smem, lam/scores in regs.
// LAST: after the iterations, emit u directly from smem (no state writeback).
// NBIS is a compile-time constant (runtime trip count cost ~30% in R12).
template <int NBIS, bool FIRST, bool LAST>
__global__ void __launch_bounds__(320, 3) fused_admm(const float* __restrict__ scores,
                                                     float* __restrict__ out,
                                                     int p, int T)
{
    __shared__ float s_msg[2][N_ROWS][SMS];

    const int t = threadIdx.x;
    const int r = t >> 2;                 // local row 0..79
    const int g = t & 3;                  // quarter-row, k in [16g,16g+16)
    const int b = blockIdx.x >> 3;
    const int c0 = (blockIdx.x & 7) << 6;
    const int c = (c0 - HALO + r) & (CC - 1);
    const int grow = ((b << 9) + c) * KK + (g << 4);   // global row-slice offset

    // ---- scores into registers (window is 16-aligned, never straddles NV) ----
    float sc[16];
    {
        const int nb = ((c << 5) + (g << 4)) & (NV - 1);
        const float4* sp = (const float4*)(scores + b * NV + nb);
#pragma unroll
        for (int q = 0; q < 4; q++) {
            float4 v = sp[q];
            sc[4 * q] = v.x; sc[4 * q + 1] = v.y; sc[4 * q + 2] = v.z; sc[4 * q + 3] = v.w;
        }
    }

    // ---- lam into registers, msg into smem buffer 0 ----
    float lam[16];
    if (FIRST) {
#pragma unroll
        for (int k = 0; k < 16; k++) lam[k] = 0.f;
        float4* d = (float4*)&s_msg[0][r][g << 4];
#pragma unroll
        for (int q = 0; q < 4; q++) d[q] = make_float4(0.f, 0.f, 0.f, 0.f);
    } else {
        const float4* lp = (const float4*)(g_lam[p] + grow);
        const float4* mp = (const float4*)(g_msg[p] + grow);
        float4* d = (float4*)&s_msg[0][r][g << 4];
#pragma unroll
        for (int q = 0; q < 4; q++) {
            float4 lv = lp[q];
            lam[4 * q] = lv.x; lam[4 * q + 1] = lv.y; lam[4 * q + 2] = lv.z; lam[4 * q + 3] = lv.w;
            d[q] = mp[q];
        }
    }
    __syncthreads();

    // neighbor row (clamped; clamped rows are halo-garbage and never written back)
    const int rn = (g < 2) ? ((r > 0) ? r - 1 : 0) : ((r < N_ROWS - 1) ? r + 1 : N_ROWS - 1);
    const int kn = (g < 2) ? ((g << 4) + 32) : ((g - 2) << 4);

    for (int it = 0; it < T; ++it) {
        const int sb = it & 1;
        const float4* mo = (const float4*)&s_msg[sb][r][g << 4];
        const float4* mn = (const float4*)&s_msg[sb][rn][kn];

        float a[16];
#pragma unroll
        for (int q = 0; q < 4; q++) {
            float4 o = mo[q];
            float4 n = mn[q];
            a[4 * q + 0] = __saturatef((sc[4 * q + 0] + o.x + n.x) * 0.5f) + lam[4 * q + 0];
            a[4 * q + 1] = __saturatef((sc[4 * q + 1] + o.y + n.y) * 0.5f) + lam[4 * q + 1];
            a[4 * q + 2] = __saturatef((sc[4 * q + 2] + o.z + n.z) * 0.5f) + lam[4 * q + 2];
            a[4 * q + 3] = __saturatef((sc[4 * q + 3] + o.w + n.w) * 0.5f) + lam[4 * q + 3];
        }

        // feasibility
        float f0 = 0.f, f1 = 0.f, f2 = 0.f, f3 = 0.f;
#pragma unroll
        for (int k = 0; k < 16; k += 4) {
            f0 += __saturatef(a[k]);     f1 += __saturatef(a[k + 1]);
            f2 += __saturatef(a[k + 2]); f3 += __saturatef(a[k + 3]);
        }
        const bool feas = qsum((f0 + f1) + (f2 + f3)) <= BUDGETF;

        float tau = 0.f;
        if (!__all_sync(0xffffffffu, feas)) {
            // Infeasible row => s(0) = sum(sat(a)) > budget, so lo = 0 is a
            // valid lower bracket; s(max(a)) = 0 < budget for the upper.
            float mx1 = fmaxf(fmaxf(a[0], a[1]), fmaxf(a[2], a[3]));
#pragma unroll
            for (int k = 4; k < 16; k += 4)
                mx1 = fmaxf(mx1, fmaxf(fmaxf(a[k], a[k + 1]), fmaxf(a[k + 2], a[k + 3])));
            float lo = 0.0f;
            float hi = qmax(mx1);

#pragma unroll 1
            for (int qq = 0; qq < NBIS; ++qq) {
                const float mid = 0.5f * (lo + hi);
                float t0 = 0.f, t1 = 0.f, t2 = 0.f, t3 = 0.f;
#pragma unroll
                for (int k = 0; k < 16; k += 4) {
                    t0 += __saturatef(a[k] - mid);
                    t1 += __saturatef(a[k + 1] - mid);
                    t2 += __saturatef(a[k + 2] - mid);
                    t3 += __saturatef(a[k + 3] - mid);
                }
                const float s = qsum((t0 + t1) + (t2 + t3));   // group-uniform
                if (s > BUDGETF) lo = mid; else hi = mid;
            }
            const float tau0 = 0.5f * (lo + hi);

            // Newton polish on the active set (matches reference)
            float na = 0.f, gs = 0.f;
#pragma unroll
            for (int k = 0; k < 16; k++) {
                const float d = a[k] - tau0;
                na += (d > 0.f && d < 1.f) ? 1.f : 0.f;
                gs += __saturatef(d);
            }
            const float nact = fmaxf(qsum(na), 1.0f);
            tau = tau0 + (qsum(gs) - BUDGETF) / nact;
        }

        // z, lam' = a - z, msg' = 2z - a
        float4* dst = (float4*)&s_msg[sb ^ 1][r][g << 4];
#pragma unroll
        for (int q = 0; q < 4; q++) {
            float mg[4];
#pragma unroll
            for (int j = 0; j < 4; j++) {
                const float ak = a[4 * q + j];
                const float zz = feas ? __saturatef(ak) : __saturatef(ak - tau);
                lam[4 * q + j] = ak - zz;
                mg[j] = zz - (ak - zz);
            }
            dst[q] = make_float4(mg[0], mg[1], mg[2], mg[3]);
        }
        __syncthreads();
    }

    if (!LAST) {
        // ---- write back valid rows only ----
        if (r >= HALO && r < HALO + 64) {
            const int fb = T & 1;
            float4* gm = (float4*)(g_msg[p ^ 1] + grow);
            float4* gl = (float4*)(g_lam[p ^ 1] + grow);
            const float4* sm = (const float4*)&s_msg[fb][r][g << 4];
#pragma unroll
            for (int q = 0; q < 4; q++) {
                gm[q] = sm[q];
                gl[q] = make_float4(lam[4 * q], lam[4 * q + 1], lam[4 * q + 2], lam[4 * q + 3]);
            }
        }
    } else {
        // ---- emit u directly: u[b, 32c + j] = sat((scores + msg[c][j] + msg[c-1][j+32])/2)
        // thread (r, g), r in [HALO, HALO+64): 8 outputs j = 8g .. 8g+7.
        if (r >= HALO && r < HALO + 64) {
            const int fb = T & 1;
            const float* m_c  = &s_msg[fb][r][g << 3];          // msg[c][8g + jj], 8g<32
            const float* m_cm = &s_msg[fb][r - 1][(g << 3) + 32];
            const int n0 = (c << 5) + (g << 3);                  // c < 512 so n0 < NV
            const float4* sp = (const float4*)(scores + b * NV + n0);
            float4* op = (float4*)(out + b * NV + n0);
#pragma unroll
            for (int q = 0; q < 2; q++) {
                float4 sv = sp[q];
                float4 u;
                u.x = __saturatef((sv.x + m_c[4 * q + 0] + m_cm[4 * q + 0]) * 0.5f);
                u.y = __saturatef((sv.y + m_c[4 * q + 1] + m_cm[4 * q + 1]) * 0.5f);
                u.z = __saturatef((sv.z + m_c[4 * q + 2] + m_cm[4 * q + 2]) * 0.5f);
                u.w = __saturatef((sv.w + m_c[4 * q + 3] + m_cm[4 * q + 3]) * 0.5f);
                op[q] = u;
            }
        }
    }
}

extern "C" void kernel_launch(void* const* d_in, const int* in_sizes, int n_in,
                              void* d_out, int out_size)
{
    const float* scores = (const float*)d_in[0];
    if (n_in > 1 && in_sizes[0] == CC * KK) scores = (const float*)d_in[1];
    float* out = (float*)d_out;

    // 25 iterations = 8 + 8 + 8 + 1; last launch emits u directly.
    // NBIS: 15 mid-trajectory (accuracy validated in R12: rel_err 2.1e-7),
    //       18 for the final, output-determining iteration.
    fused_admm<15, true , false><<<512, 320>>>(scores, out, 0, 8);   // writes parity 1
    fused_admm<15, false, false><<<512, 320>>>(scores, out, 1, 8);   // writes parity 0
    fused_admm<15, false, false><<<512, 320>>>(scores, out, 0, 8);   // writes parity 1
    fused_admm<18, false, true ><<<512, 320>>>(scores, out, 1, 1);   // emits u
}